// round 16
// baseline (speedup 1.0000x reference)
#include <cuda_runtime.h>
#include <cuda_fp16.h>
#include <cstdint>

// KPConv, GB300 (sm_103a; harness compiles at compute_103 -> no tcgen05).
// Round 16: R15 + two-row interleaved prefetch (compile-time structure).
// Per warp pair (rows A,B): both gather chains issued back-to-back, consume A
// with wait_group 1 (B in flight), then consume B with wait_group 0.
// Serial tail path for rows with >16 edges. Numerics identical to R15.

#define KP       15
#define FDIM     32
#define CDIM     64
#define KK       480
#define BM       32
#define THREADS  256
#define NSTEP    30
#define NPTS     40000
#define INV_EXTENT (1.0f / 0.6f)

#define ROW_STRIDE 976                    // 480 fp16 = 960B + 16B pad
#define A_BYTES    (BM * ROW_STRIDE)      // 31232 (dynamic smem)

#define F_STRIDE_H 40                     // f_s row stride in halves (80B, conflict-free)
#define W_STRIDE_H 24                     // w_s row stride in halves (48B, conflict-free)

__device__ uint4  g_bfrag[4 * NSTEP * 32];
__device__ int    g_rowptr[40001];
__device__ __half g_feat16[NPTS * FDIM];
__device__ float4 g_pts4[NPTS];

__device__ __forceinline__ uint32_t smem_u32(const void* p) {
    uint32_t a;
    asm("{ .reg .u64 t; cvta.to.shared.u64 t, %1; cvt.u32.u64 %0, t; }" : "=r"(a) : "l"(p));
    return a;
}
__device__ __forceinline__ void ldsm4(uint32_t addr, uint32_t* r) {
    asm volatile("ldmatrix.sync.aligned.m8n8.x4.shared.b16 {%0,%1,%2,%3}, [%4];"
                 : "=r"(r[0]), "=r"(r[1]), "=r"(r[2]), "=r"(r[3]) : "r"(addr));
}
__device__ __forceinline__ void ldsm4t(uint32_t addr, uint32_t* r) {
    asm volatile("ldmatrix.sync.aligned.m8n8.x4.trans.shared.b16 {%0,%1,%2,%3}, [%4];"
                 : "=r"(r[0]), "=r"(r[1]), "=r"(r[2]), "=r"(r[3]) : "r"(addr));
}
__device__ __forceinline__ void mma16816h(float* d, const uint32_t* a,
                                          uint32_t b0, uint32_t b1) {
    asm volatile(
        "mma.sync.aligned.m16n8k16.row.col.f32.f16.f16.f32 "
        "{%0,%1,%2,%3}, {%4,%5,%6,%7}, {%8,%9}, {%0,%1,%2,%3};"
        : "+f"(d[0]), "+f"(d[1]), "+f"(d[2]), "+f"(d[3])
        : "r"(a[0]), "r"(a[1]), "r"(a[2]), "r"(a[3]), "r"(b0), "r"(b1));
}
__device__ __forceinline__ void cpa16(uint32_t dst, const void* src) {
    asm volatile("cp.async.ca.shared.global [%0], [%1], 16;" :: "r"(dst), "l"(src));
}

// ================= prep: bfrag + feat16 + pts4 + rowptr =================
__global__ void prep_kernel(const float* __restrict__ kv,
                            const float* __restrict__ features,
                            const float* __restrict__ points,
                            const int* __restrict__ sid,
                            int E, int M, int NF,
                            int nf16_blocks, int pts_blocks) {
    int b = blockIdx.x;
    int t = threadIdx.x;
    if (b == 0) {
        for (int i = t; i < 4 * NSTEP * 32; i += 256) {
            int l  = i & 31;
            int s  = (i >> 5) % NSTEP;
            int wn = i / (NSTEP * 32);
            int n0 = wn * 16 + (l >> 2);
            int kb = s * 16 + 2 * (l & 3);
            auto h2 = [&](int n, int k) -> uint32_t {
                __half2 p = __halves2half2(__float2half_rn(kv[k * CDIM + n]),
                                           __float2half_rn(kv[(k + 1) * CDIM + n]));
                return *(uint32_t*)&p;
            };
            uint4 v;
            v.x = h2(n0,     kb);
            v.y = h2(n0 + 8, kb);
            v.z = h2(n0,     kb + 8);
            v.w = h2(n0 + 8, kb + 8);
            g_bfrag[i] = v;
        }
    } else if (b <= nf16_blocks) {
        int i4 = ((b - 1) * 256 + t) * 4;
        if (i4 < NF) {
            float4 v = *(const float4*)(features + i4);
            __half2 h0 = __floats2half2_rn(v.x, v.y);
            __half2 h1 = __floats2half2_rn(v.z, v.w);
            *(uint2*)(g_feat16 + i4) = make_uint2(*(uint32_t*)&h0, *(uint32_t*)&h1);
        }
    } else if (b <= nf16_blocks + pts_blocks) {
        int i = (b - 1 - nf16_blocks) * 256 + t;
        if (i < NPTS)
            g_pts4[i] = make_float4(points[i * 3], points[i * 3 + 1],
                                    points[i * 3 + 2], 0.f);
    } else {
        int i = (b - 1 - nf16_blocks - pts_blocks) * 256 + t;
        if (i >= E) return;
        int s  = __ldg(sid + i);
        int sp = (i == 0) ? -1 : __ldg(sid + i - 1);
        for (int m = sp + 1; m <= s; m++) g_rowptr[m] = i;
        if (i == E - 1)
            for (int m = s + 1; m <= M; m++) g_rowptr[m] = E;
    }
}

// ================= main: fused agg(MMA, paired) + GEMM =================
__global__ __launch_bounds__(THREADS, 2) void kpconv_main_kernel(
    const float* __restrict__ outp,
    const int*   __restrict__ nbr,
    const float* __restrict__ kpts,
    float*       __restrict__ out,
    int M)
{
    extern __shared__ __align__(128) char sm[];         // A tile [32][976B]
    __shared__ __half w_s[8][16 * W_STRIDE_H];          // per-warp W[e][k]
    __shared__ __half f_s[8][2][16 * F_STRIDE_H];       // per-warp, 2 buffers

    const uint32_t sbase = smem_u32(sm);
    const int tid  = threadIdx.x;
    const int warp = tid >> 5;
    const int lane = tid & 31;
    const int m0   = blockIdx.x * BM;

    const int eidx  = lane & 15;
    const int khalf = lane >> 4;

    // kernel-point constants in registers
    float4 kq[8];
    #pragma unroll
    for (int kk = 0; kk < 8; kk++) {
        int k = khalf * 8 + kk;
        if (k < KP) {
            float x = __ldg(kpts + k * 3 + 0);
            float y = __ldg(kpts + k * 3 + 1);
            float z = __ldg(kpts + k * 3 + 2);
            kq[kk] = make_float4(x, y, z, fmaf(x, x, fmaf(y, y, z * z)));
        } else {
            kq[kk] = make_float4(0.f, 0.f, 0.f, 1.0e6f);
        }
    }

    // zero both feature buffers once (initial-NaN protection; stale finite data
    // later is harmless because invalid-edge weights are exactly 0)
    {
        uint4* fz = (uint4*)&f_s[warp][0][0];
        const int tot = 2 * 16 * F_STRIDE_H / 8;       // uint4 count = 160
        #pragma unroll
        for (int i = 0; i < 5; i++) {
            int idx = lane + i * 32;
            if (idx < tot) fz[idx] = make_uint4(0, 0, 0, 0);
        }
    }
    __syncwarp();

    const uint32_t wbase  = smem_u32(&w_s[warp][0]);
    const uint32_t fbaseA = smem_u32(&f_s[warp][0][0]);
    const uint32_t fbaseB = smem_u32(&f_s[warp][1][0]);

    const int g  = lane >> 3;
    const int lr = lane & 7;
    const uint32_t a_addr  = wbase + (uint32_t)(lr + ((g >> 1) << 3)) * (W_STRIDE_H * 2)
                           + (uint32_t)((g & 1) << 3) * 2;
    const uint32_t b_off   = (uint32_t)(lr + ((g & 1) << 3)) * (F_STRIDE_H * 2)
                           + (uint32_t)((g >> 1) << 3) * 2;
    const uint32_t b_addrA = fbaseA + b_off;
    const uint32_t b_addrB = fbaseB + b_off;
    const uint32_t f_dst_off = (uint32_t)eidx * (F_STRIDE_H * 2) + (uint32_t)khalf * 16;

    // --- helpers (all inlined; no dynamic array indexing) ---
    auto gather = [&](int base, int cnt, uint32_t fbase,
                      int& ni, float& px, float& py, float& pz) {
        ni = 0; px = 0.f; py = 0.f; pz = 0.f;
        bool v = (eidx < cnt);
        if (v) {
            ni = __ldg(nbr + base + eidx);
            float4 p = __ldg(&g_pts4[ni]);
            px = p.x; py = p.y; pz = p.z;
        }
        if (v) {
            const __half* srcf = g_feat16 + (size_t)ni * FDIM;
            cpa16(fbase + f_dst_off,      srcf + khalf * 8);
            cpa16(fbase + f_dst_off + 32, srcf + 16 + khalf * 8);
        }
        asm volatile("cp.async.commit_group;");
    };

    auto wphase = [&](float px, float py, float pz,
                      float ox, float oy, float oz, int cnt) {
        bool v = (eidx < cnt);
        float rx = px - ox, ry = py - oy, rz = pz - oz;
        float relsq = fmaf(rx, rx, fmaf(ry, ry, rz * rz));
        float w[8];
        #pragma unroll
        for (int kk = 0; kk < 8; kk++) {
            float4 q = kq[kk];
            float d  = fmaf(rx, q.x, fmaf(ry, q.y, rz * q.z));
            float sq = fmaxf(fmaf(-2.f, d, relsq + q.w), 0.f);
            float wv = fmaxf(fmaf(sqrtf(sq), -INV_EXTENT, 1.f), 0.f);
            w[kk] = v ? wv : 0.f;
        }
        __half2 h0 = __floats2half2_rn(w[0], w[1]);
        __half2 h1 = __floats2half2_rn(w[2], w[3]);
        __half2 h2 = __floats2half2_rn(w[4], w[5]);
        __half2 h3 = __floats2half2_rn(w[6], w[7]);
        *(uint4*)(w_s[warp] + eidx * W_STRIDE_H + khalf * 8) =
            make_uint4(*(uint32_t*)&h0, *(uint32_t*)&h1,
                       *(uint32_t*)&h2, *(uint32_t*)&h3);
    };

    auto do_mma = [&](uint32_t baddr, float (&ca)[4][4]) {
        uint32_t a[4];
        ldsm4t(a_addr, a);
        uint32_t b0[4], b1[4];
        ldsm4t(baddr,      b0);
        ldsm4t(baddr + 32, b1);
        mma16816h(ca[0], a, b0[0], b0[1]);
        mma16816h(ca[1], a, b0[2], b0[3]);
        mma16816h(ca[2], a, b1[0], b1[1]);
        mma16816h(ca[3], a, b1[2], b1[3]);
    };

    auto flush = [&](int r, float (&ca)[4][4]) {
        char* ar = sm + r * ROW_STRIDE;
        const int kp1 = lane >> 2;
        const int f0  = (lane & 3) * 2;
        #pragma unroll
        for (int nb = 0; nb < 4; nb++) {
            int f = nb * 8 + f0;
            __half2 hA = __floats2half2_rn(ca[nb][0], ca[nb][1]);
            *(__half2*)(ar + (kp1 * 32 + f) * 2) = hA;
            if (kp1 < 7) {
                __half2 hB = __floats2half2_rn(ca[nb][2], ca[nb][3]);
                *(__half2*)(ar + ((kp1 + 8) * 32 + f) * 2) = hB;
            }
        }
    };

    // serial tail for rows with >16 edges (rare)
    auto tail = [&](int s, int e, uint32_t fbase, uint32_t baddr,
                    float ox, float oy, float oz, float (&ca)[4][4]) {
        for (int base2 = s + 16; base2 < e; base2 += 16) {
            int c2 = e - base2; if (c2 > 16) c2 = 16;
            int ni2; float px2, py2, pz2;
            gather(base2, c2, fbase, ni2, px2, py2, pz2);
            wphase(px2, py2, pz2, ox, oy, oz, c2);
            __syncwarp();
            asm volatile("cp.async.wait_group 0;");
            __syncwarp();
            do_mma(baddr, ca);
        }
    };

    // ---------------- Phase A: paired rows ----------------
    #pragma unroll
    for (int pr = 0; pr < 2; pr++) {
        const int rA = warp + (2 * pr) * 8;
        const int rB = warp + (2 * pr + 1) * 8;
        const int mA = m0 + rA;
        const int mB = m0 + rB;

        int sA = 0, eA = 0, sB = 0, eB = 0;
        float oxA = 0.f, oyA = 0.f, ozA = 0.f, oxB = 0.f, oyB = 0.f, ozB = 0.f;
        if (mA < M) {
            sA = __ldg(g_rowptr + mA); eA = __ldg(g_rowptr + mA + 1);
            oxA = __ldg(outp + mA * 3 + 0);
            oyA = __ldg(outp + mA * 3 + 1);
            ozA = __ldg(outp + mA * 3 + 2);
        }
        if (mB < M) {
            sB = __ldg(g_rowptr + mB); eB = __ldg(g_rowptr + mB + 1);
            oxB = __ldg(outp + mB * 3 + 0);
            oyB = __ldg(outp + mB * 3 + 1);
            ozB = __ldg(outp + mB * 3 + 2);
        }
        int cntA = eA - sA; if (cntA > 16) cntA = 16; if (cntA < 0) cntA = 0;
        int cntB = eB - sB; if (cntB > 16) cntB = 16; if (cntB < 0) cntB = 0;

        // both prefetch chains in flight
        int niA; float pxA, pyA, pzA;
        gather(sA, cntA, fbaseA, niA, pxA, pyA, pzA);     // group 1-pending after B
        int niB; float pxB, pyB, pzB;
        gather(sB, cntB, fbaseB, niB, pxB, pyB, pzB);     // 2 groups pending

        // ---- consume A (B still in flight) ----
        float caA[4][4];
        #pragma unroll
        for (int nb = 0; nb < 4; nb++)
            #pragma unroll
            for (int i = 0; i < 4; i++) caA[nb][i] = 0.f;

        wphase(pxA, pyA, pzA, oxA, oyA, ozA, cntA);
        __syncwarp();
        asm volatile("cp.async.wait_group 1;");
        __syncwarp();
        do_mma(b_addrA, caA);
        tail(sA, eA, fbaseA, b_addrA, oxA, oyA, ozA, caA);
        flush(rA, caA);

        // ---- consume B ----
        float caB[4][4];
        #pragma unroll
        for (int nb = 0; nb < 4; nb++)
            #pragma unroll
            for (int i = 0; i < 4; i++) caB[nb][i] = 0.f;

        wphase(pxB, pyB, pzB, oxB, oyB, ozB, cntB);
        __syncwarp();
        asm volatile("cp.async.wait_group 0;");
        __syncwarp();
        do_mma(b_addrB, caB);
        tail(sB, eB, fbaseB, b_addrB, oxB, oyB, ozB, caB);
        flush(rB, caB);
    }
    __syncthreads();

    // ---------------- Phase B: GEMM [32,480] x [64,480]^T (unchanged) ----------------
    const int warp_m = warp & 1;
    const int warp_n = warp >> 1;
    const uint32_t abase = sbase + (uint32_t)(warp_m * 16 + (lane & 15)) * ROW_STRIDE
                         + (uint32_t)(lane >> 4) * 16;
    const uint4* bf = g_bfrag + (size_t)warp_n * NSTEP * 32 + lane;

    float acc[2][4];
    #pragma unroll
    for (int nt = 0; nt < 2; nt++)
        #pragma unroll
        for (int i = 0; i < 4; i++) acc[nt][i] = 0.f;

    #pragma unroll
    for (int s = 0; s < NSTEP; s++) {
        uint32_t a[4];
        ldsm4(abase + (uint32_t)s * 32, a);
        uint4 f = __ldg(bf + s * 32);
        mma16816h(acc[0], a, f.x, f.z);
        mma16816h(acc[1], a, f.y, f.w);
    }

    const int qr = lane >> 2;
    const int qc = (lane & 3) * 2;
    #pragma unroll
    for (int nt = 0; nt < 2; nt++) {
        int r0 = m0 + warp_m * 16 + qr;
        int cc = warp_n * 16 + nt * 8 + qc;
        if (r0 < M)
            *(float2*)(out + (size_t)r0 * CDIM + cc) = make_float2(acc[nt][0], acc[nt][1]);
        if (r0 + 8 < M)
            *(float2*)(out + (size_t)(r0 + 8) * CDIM + cc) = make_float2(acc[nt][2], acc[nt][3]);
    }
}

// ================= launch =================
extern "C" void kernel_launch(void* const* d_in, const int* in_sizes, int n_in,
                              void* d_out, int out_size) {
    const float* points   = (const float*)d_in[0];
    const float* features = (const float*)d_in[1];
    const float* outp     = (const float*)d_in[2];
    const int*   nbr      = (const int*)d_in[3];
    const int*   sid      = (const int*)d_in[4];
    const float* kpts     = (const float*)d_in[5];
    const float* kv       = (const float*)d_in[6];
    float*       out      = (float*)d_out;

    int E  = in_sizes[3];
    int NF = in_sizes[1];
    int M  = out_size / CDIM;

    static bool attr_set = false;
    if (!attr_set) {
        cudaFuncSetAttribute(kpconv_main_kernel,
                             cudaFuncAttributeMaxDynamicSharedMemorySize,
                             A_BYTES);
        attr_set = true;
    }

    int nf16_blocks = (NF / 4 + 255) / 256;
    int pts_blocks  = (NPTS + 255) / 256;
    int prep_blocks = 1 + nf16_blocks + pts_blocks + (E + 255) / 256;
    prep_kernel<<<prep_blocks, 256>>>(kv, features, points, sid, E, M, NF,
                                      nf16_blocks, pts_blocks);
    int blocks = (M + BM - 1) / BM;
    kpconv_main_kernel<<<blocks, THREADS, A_BYTES>>>(outp, nbr, kpts, out, M);
}